// round 16
// baseline (speedup 1.0000x reference)
#include <cuda_runtime.h>
#include <cuda_fp16.h>
#include <cstdint>
#include <cstddef>

// Problem dims
#define G_N 8
#define D_N 1024
#define H_N 2048
#define O_N 1024
#define B_N 8192   // rows per group (65536 / 8)

// ---------------- scratch (static device arrays; allocation-free) ----------------
__device__ __align__(1024) __half g_xh  [(size_t)65536 * 1024];     // x fp16, group-major [g][b][d]
__device__ __align__(1024) __half g_wgh [(size_t)8 * 2048 * 1024];  // Wg fp16 [g][h][d]
__device__ __align__(1024) __half g_wuh [(size_t)8 * 2048 * 1024];  // Wu fp16 [g][h][d]
__device__ __align__(1024) __half g_wdh [(size_t)8 * 1024 * 2048];  // Wd fp16 [g][o][h]
__device__ __align__(1024) __half g_hid [(size_t)65536 * 2048];     // hidden fp16 [g][b][h]

// ---------------- helpers ----------------
__device__ __forceinline__ uint32_t smem_u32(const void* p) {
    return (uint32_t)__cvta_generic_to_shared(p);
}

// BK=64 tile: rows are 64 halves (128B = 8 x 16B chunks). SW128-style swizzle:
// phys(r, c) = r*128 + ((c ^ (r & 7)) << 4), c in [0,8)
__device__ __forceinline__ uint32_t swz64(int r, int c) {
    return (uint32_t)(r * 128 + ((c ^ (r & 7)) << 4));
}

__device__ __forceinline__ void cpa16(uint32_t s, const void* g) {
    asm volatile("cp.async.cg.shared.global [%0], [%1], 16;" :: "r"(s), "l"(g));
}
__device__ __forceinline__ void cpa_commit() { asm volatile("cp.async.commit_group;" ::: "memory"); }
__device__ __forceinline__ void cpa_wait1()  { asm volatile("cp.async.wait_group 1;"  ::: "memory"); }
__device__ __forceinline__ void cpa_wait0()  { asm volatile("cp.async.wait_group 0;"  ::: "memory"); }

__device__ __forceinline__ void ldsm_x4(uint32_t& r0, uint32_t& r1, uint32_t& r2, uint32_t& r3,
                                        uint32_t addr) {
    asm volatile("ldmatrix.sync.aligned.m8n8.x4.shared.b16 {%0,%1,%2,%3}, [%4];"
                 : "=r"(r0), "=r"(r1), "=r"(r2), "=r"(r3) : "r"(addr));
}

__device__ __forceinline__ void mma16816(float* c, const uint32_t* a, const uint32_t* b) {
    asm volatile(
        "mma.sync.aligned.m16n8k16.row.col.f32.f16.f16.f32 "
        "{%0,%1,%2,%3}, {%4,%5,%6,%7}, {%8,%9}, {%0,%1,%2,%3};"
        : "+f"(c[0]), "+f"(c[1]), "+f"(c[2]), "+f"(c[3])
        : "r"(a[0]), "r"(a[1]), "r"(a[2]), "r"(a[3]), "r"(b[0]), "r"(b[1]));
}

__device__ __forceinline__ float silu_f(float v) {
    return __fdividef(v, 1.0f + __expf(-v));
}

// ---------------- pass 0: conversions (2 x float4 per thread) ----------------
__global__ void cvt_x_kernel(const float* __restrict__ x) {
    size_t base = ((size_t)blockIdx.x * 256 + threadIdx.x) * 8;
    #pragma unroll
    for (int u = 0; u < 2; u++) {
        size_t i = base + u * 4;
        float4 v = *reinterpret_cast<const float4*>(x + i);
        int row = (int)(i >> 10);
        int col = (int)(i & 1023);
        int g = row & 7, b = row >> 3;
        __half2 h0 = __floats2half2_rn(v.x, v.y);
        __half2 h1 = __floats2half2_rn(v.z, v.w);
        __half2* d = reinterpret_cast<__half2*>(g_xh + (((size_t)(g * B_N + b)) << 10) + col);
        d[0] = h0; d[1] = h1;
    }
}

__global__ void cvt_w_all_kernel(const float* __restrict__ Wg,
                                 const float* __restrict__ Wu,
                                 const float* __restrict__ Wd) {
    int which = blockIdx.x >> 13;                 // 8192 blocks per weight
    const float* s = (which == 0) ? Wg : (which == 1) ? Wu : Wd;
    __half* dst    = (which == 0) ? g_wgh : (which == 1) ? g_wuh : g_wdh;
    size_t base = ((size_t)(blockIdx.x & 8191) * 256 + threadIdx.x) * 8;
    #pragma unroll
    for (int u = 0; u < 2; u++) {
        size_t i = base + u * 4;
        float4 v = *reinterpret_cast<const float4*>(s + i);
        __half2 h0 = __floats2half2_rn(v.x, v.y);
        __half2 h1 = __floats2half2_rn(v.z, v.w);
        __half2* d = reinterpret_cast<__half2*>(dst + i);
        d[0] = h0; d[1] = h1;
    }
}

// ---------------- pass 1: FUSED gate+up -> SwiGLU -> g_hid ----------------
// CTA tile 128(M)x64(N_H), BK=64, 128 threads (4 warps as 2Mx2N), warp tile 64x32.
// Dual accumulators (gate+up). 3-stage cp.async; prefetch issued at TOP of chunk
// so LDGSTS issue + DRAM latency overlap the whole MMA block.
#define GU_A_STAGE (128 * 64 * 2)               // 16KB
#define GU_B_STAGE (64 * 64 * 2)                // 8KB per B matrix
#define GU_STAGE   (GU_A_STAGE + 2 * GU_B_STAGE) // 32KB
#define GU_SMEM    (3 * GU_STAGE)               // 96KB

__global__ void __launch_bounds__(128, 2) gemm_gu_kernel() {
    extern __shared__ __align__(1024) __half smem[];

    int tid = threadIdx.x, l = tid & 31, wid = tid >> 5;
    int wm = wid & 1, wn = wid >> 1;            // 2x2 warp grid
    int g = blockIdx.z, m0 = blockIdx.y * 128, n0 = blockIdx.x * 64;

    const __half* A  = g_xh  + ((size_t)g * B_N + m0) * D_N;
    const __half* Bg = g_wgh + ((size_t)g * H_N + n0) * D_N;
    const __half* Bu = g_wuh + ((size_t)g * H_N + n0) * D_N;

    uint32_t sbase = smem_u32(smem);
    uint32_t sAu[3], sBgu[3], sBuu[3];
    #pragma unroll
    for (int s = 0; s < 3; s++) {
        sAu[s]  = sbase + s * GU_STAGE;
        sBgu[s] = sAu[s] + GU_A_STAGE;
        sBuu[s] = sBgu[s] + GU_B_STAGE;
    }

    float accG[4][4][4], accU[4][4][4];
    #pragma unroll
    for (int i = 0; i < 4; i++)
        #pragma unroll
        for (int j = 0; j < 4; j++)
            #pragma unroll
            for (int q = 0; q < 4; q++) { accG[i][j][q] = 0.0f; accU[i][j][q] = 0.0f; }

    auto load_tiles = [&](int kc, int s) {
        int k0 = kc * 64;
        #pragma unroll
        for (int i = 0; i < 8; i++) {        // A: 128 rows x 8 chunks = 1024
            int linear = tid + i * 128;
            int r = linear >> 3, c = linear & 7;
            cpa16(sAu[s] + swz64(r, c), A + (size_t)r * D_N + k0 + c * 8);
        }
        #pragma unroll
        for (int i = 0; i < 4; i++) {        // Bg/Bu: 64 rows x 8 chunks = 512 each
            int linear = tid + i * 128;
            int r = linear >> 3, c = linear & 7;
            uint32_t so = swz64(r, c);
            size_t go = (size_t)r * D_N + k0 + c * 8;
            cpa16(sBgu[s] + so, Bg + go);
            cpa16(sBuu[s] + so, Bu + go);
        }
    };

    const int NKC = D_N / 64;                // 16
    load_tiles(0, 0); cpa_commit();
    load_tiles(1, 1); cpa_commit();
    cpa_wait1();
    __syncthreads();

    int s = 0, sl = 2;
    for (int kc = 0; kc < NKC; kc++) {
        // prefetch kc+2 FIRST: stage sl was last read in chunk kc-1; safe after
        // the barrier that ended chunk kc-1. Overlaps with all MMAs below.
        if (kc + 2 < NKC) { load_tiles(kc + 2, sl); cpa_commit(); }

        #pragma unroll
        for (int ks = 0; ks < 4; ks++) {     // 4 k-steps of 16 per chunk
            uint32_t af[4][4], bg[4][2], bu[4][2];
            #pragma unroll
            for (int i = 0; i < 4; i++) {    // A: m16k16 fragments (64 rows)
                int r = wm * 64 + i * 16 + (l & 15);
                int c = ks * 2 + (l >> 4);
                ldsm_x4(af[i][0], af[i][1], af[i][2], af[i][3], sAu[s] + swz64(r, c));
            }
            #pragma unroll
            for (int p = 0; p < 2; p++) {    // B: two 8-row blocks per x4 (32 cols)
                int j = 2 * p;
                int r = wn * 32 + j * 8 + ((l & 16) >> 1) + (l & 7);
                int c = ks * 2 + ((l >> 3) & 1);
                uint32_t so = swz64(r, c);
                ldsm_x4(bg[j][0], bg[j][1], bg[j + 1][0], bg[j + 1][1], sBgu[s] + so);
                ldsm_x4(bu[j][0], bu[j][1], bu[j + 1][0], bu[j + 1][1], sBuu[s] + so);
            }
            #pragma unroll
            for (int i = 0; i < 4; i++)
                #pragma unroll
                for (int j = 0; j < 4; j++) {
                    mma16816(accG[i][j], af[i], bg[j]);
                    mma16816(accU[i][j], af[i], bu[j]);
                }
        }

        // tail: once no new groups are issued, wait1 no longer guarantees
        // chunk kc+1 residency -> use wait0 from kc == NKC-2 onward.
        if (kc + 2 < NKC) cpa_wait1();
        else              cpa_wait0();
        __syncthreads();

        s  = (s  == 2) ? 0 : s  + 1;
        sl = (sl == 2) ? 0 : sl + 1;
    }

    // epilogue: silu(gate)*up (fp32, unrounded) -> fp16 hidden
    int rq = l >> 2;          // 0..7
    int cq = 2 * (l & 3);     // 0,2,4,6
    #pragma unroll
    for (int i = 0; i < 4; i++) {
        int mrow0 = m0 + wm * 64 + i * 16 + rq;
        #pragma unroll
        for (int j = 0; j < 4; j++) {
            int col = n0 + wn * 32 + j * 8 + cq;
            float h0 = silu_f(accG[i][j][0]) * accU[i][j][0];
            float h1 = silu_f(accG[i][j][1]) * accU[i][j][1];
            float h2 = silu_f(accG[i][j][2]) * accU[i][j][2];
            float h3 = silu_f(accG[i][j][3]) * accU[i][j][3];
            __half2* p0 = reinterpret_cast<__half2*>(
                g_hid + ((size_t)g * B_N + mrow0) * H_N + col);
            __half2* p1 = reinterpret_cast<__half2*>(
                g_hid + ((size_t)g * B_N + mrow0 + 8) * H_N + col);
            *p0 = __floats2half2_rn(h0, h1);
            *p1 = __floats2half2_rn(h2, h3);
        }
    }
}

// ---------------- pass 2: down projection ----------------
// CTA tile 128x128, BK=64, 128 threads (4 warps as 2Mx2N), warp tile 64x64.
#define A_STAGE (128 * 64 * 2)              // 16KB
#define B_STAGE (128 * 64 * 2)              // 16KB
#define STAGE_BYTES (A_STAGE + B_STAGE)     // 32KB
#define SMEM_DYN (3 * STAGE_BYTES)          // 96KB

__global__ void __launch_bounds__(128, 2) gemm_d_kernel(float* __restrict__ out) {
    extern __shared__ __align__(1024) __half smem[];

    int tid = threadIdx.x, l = tid & 31, wid = tid >> 5;
    int wm = wid & 1, wn = wid >> 1;            // 2x2 warp grid
    int g = blockIdx.z, m0 = blockIdx.y * 128, n0 = blockIdx.x * 128;

    const __half* A = g_hid + ((size_t)g * B_N + m0) * H_N;
    const __half* B = g_wdh + ((size_t)g * O_N + n0) * H_N;

    uint32_t sbase = smem_u32(smem);
    uint32_t sAu[3] = { sbase,           sbase + STAGE_BYTES,           sbase + 2 * STAGE_BYTES };
    uint32_t sBu[3] = { sbase + A_STAGE, sbase + STAGE_BYTES + A_STAGE, sbase + 2 * STAGE_BYTES + A_STAGE };

    float acc[4][8][4];
    #pragma unroll
    for (int i = 0; i < 4; i++)
        #pragma unroll
        for (int j = 0; j < 8; j++)
            #pragma unroll
            for (int q = 0; q < 4; q++) acc[i][j][q] = 0.0f;

    auto load_tiles = [&](int kc, int s) {
        int k0 = kc * 64;
        #pragma unroll
        for (int i = 0; i < 8; i++) {
            int linear = tid + i * 128;
            int r = linear >> 3, c = linear & 7;
            cpa16(sAu[s] + swz64(r, c), A + (size_t)r * H_N + k0 + c * 8);
        }
        #pragma unroll
        for (int i = 0; i < 8; i++) {
            int linear = tid + i * 128;
            int r = linear >> 3, c = linear & 7;
            cpa16(sBu[s] + swz64(r, c), B + (size_t)r * H_N + k0 + c * 8);
        }
    };

    const int NKC = H_N / 64;               // 32
    load_tiles(0, 0); cpa_commit();
    load_tiles(1, 1); cpa_commit();
    cpa_wait1();
    __syncthreads();

    int s = 0, sl = 2;
    for (int kc = 0; kc < NKC; kc++) {
        if (kc + 2 < NKC) { load_tiles(kc + 2, sl); cpa_commit(); }

        #pragma unroll
        for (int ks = 0; ks < 4; ks++) {
            uint32_t af[4][4], bf[8][2];
            #pragma unroll
            for (int i = 0; i < 4; i++) {
                int r = wm * 64 + i * 16 + (l & 15);
                int c = ks * 2 + (l >> 4);
                ldsm_x4(af[i][0], af[i][1], af[i][2], af[i][3], sAu[s] + swz64(r, c));
            }
            #pragma unroll
            for (int p = 0; p < 4; p++) {
                int j = 2 * p;
                int r = wn * 64 + j * 8 + ((l & 16) >> 1) + (l & 7);
                int c = ks * 2 + ((l >> 3) & 1);
                ldsm_x4(bf[j][0], bf[j][1], bf[j + 1][0], bf[j + 1][1],
                        sBu[s] + swz64(r, c));
            }
            #pragma unroll
            for (int i = 0; i < 4; i++)
                #pragma unroll
                for (int j = 0; j < 8; j++)
                    mma16816(acc[i][j], af[i], bf[j]);
        }

        if (kc + 2 < NKC) cpa_wait1();
        else              cpa_wait0();
        __syncthreads();

        s  = (s  == 2) ? 0 : s  + 1;
        sl = (sl == 2) ? 0 : sl + 1;
    }

    int rq = l >> 2;
    int cq = 2 * (l & 3);
    #pragma unroll
    for (int i = 0; i < 4; i++) {
        int mrow0 = m0 + wm * 64 + i * 16 + rq;
        #pragma unroll
        for (int j = 0; j < 8; j++) {
            int col = n0 + wn * 64 + j * 8 + cq;
            float2* p0 = reinterpret_cast<float2*>(
                out + ((size_t)(mrow0 * G_N + g)) * O_N + col);
            float2* p1 = reinterpret_cast<float2*>(
                out + ((size_t)((mrow0 + 8) * G_N + g)) * O_N + col);
            *p0 = make_float2(acc[i][j][0], acc[i][j][1]);
            *p1 = make_float2(acc[i][j][2], acc[i][j][3]);
        }
    }
}

// ---------------- launcher ----------------
extern "C" void kernel_launch(void* const* d_in, const int* in_sizes, int n_in,
                              void* d_out, int out_size) {
    (void)in_sizes; (void)n_in; (void)out_size;
    const float* x  = (const float*)d_in[0];
    const float* Wg = (const float*)d_in[1];
    const float* Wu = (const float*)d_in[2];
    const float* Wd = (const float*)d_in[3];
    float* out = (float*)d_out;

    cudaFuncSetAttribute(gemm_gu_kernel, cudaFuncAttributeMaxDynamicSharedMemorySize, GU_SMEM);
    cudaFuncSetAttribute(gemm_d_kernel,  cudaFuncAttributeMaxDynamicSharedMemorySize, SMEM_DYN);

    cvt_x_kernel<<<32768, 256>>>(x);               // 8 floats per thread
    cvt_w_all_kernel<<<24576, 256>>>(Wg, Wu, Wd);  // 8192 blocks per weight

    gemm_gu_kernel<<<dim3(32, 64, 8), 128, GU_SMEM>>>();     // fused gate+up+SwiGLU
    gemm_d_kernel<<<dim3(8, 64, 8), 128, SMEM_DYN>>>(out);   // down proj
}

// round 17
// speedup vs baseline: 1.0296x; 1.0296x over previous
#include <cuda_runtime.h>
#include <cuda_fp16.h>
#include <cstdint>
#include <cstddef>

// Problem dims
#define G_N 8
#define D_N 1024
#define H_N 2048
#define O_N 1024
#define B_N 8192   // rows per group (65536 / 8)

// ---------------- scratch (static device arrays; allocation-free) ----------------
__device__ __align__(1024) __half g_xh  [(size_t)65536 * 1024];     // x fp16, group-major [g][b][d]
__device__ __align__(1024) __half g_wgh [(size_t)8 * 2048 * 1024];  // Wg fp16 [g][h][d]
__device__ __align__(1024) __half g_wuh [(size_t)8 * 2048 * 1024];  // Wu fp16 [g][h][d]
__device__ __align__(1024) __half g_wdh [(size_t)8 * 1024 * 2048];  // Wd fp16 [g][o][h]
__device__ __align__(1024) __half g_hid [(size_t)65536 * 2048];     // hidden fp16 [g][b][h]

// ---------------- helpers ----------------
__device__ __forceinline__ uint32_t smem_u32(const void* p) {
    return (uint32_t)__cvta_generic_to_shared(p);
}

// BK=64 tile: rows are 64 halves (128B = 8 x 16B chunks). SW128-style swizzle:
// phys(r, c) = r*128 + ((c ^ (r & 7)) << 4), c in [0,8)
__device__ __forceinline__ uint32_t swz64(int r, int c) {
    return (uint32_t)(r * 128 + ((c ^ (r & 7)) << 4));
}

__device__ __forceinline__ void cpa16(uint32_t s, const void* g) {
    asm volatile("cp.async.cg.shared.global [%0], [%1], 16;" :: "r"(s), "l"(g));
}
__device__ __forceinline__ void cpa_commit() { asm volatile("cp.async.commit_group;" ::: "memory"); }
__device__ __forceinline__ void cpa_wait1()  { asm volatile("cp.async.wait_group 1;"  ::: "memory"); }
__device__ __forceinline__ void cpa_wait0()  { asm volatile("cp.async.wait_group 0;"  ::: "memory"); }

__device__ __forceinline__ void ldsm_x4(uint32_t& r0, uint32_t& r1, uint32_t& r2, uint32_t& r3,
                                        uint32_t addr) {
    asm volatile("ldmatrix.sync.aligned.m8n8.x4.shared.b16 {%0,%1,%2,%3}, [%4];"
                 : "=r"(r0), "=r"(r1), "=r"(r2), "=r"(r3) : "r"(addr));
}

__device__ __forceinline__ void mma16816(float* c, const uint32_t* a, const uint32_t* b) {
    asm volatile(
        "mma.sync.aligned.m16n8k16.row.col.f32.f16.f16.f32 "
        "{%0,%1,%2,%3}, {%4,%5,%6,%7}, {%8,%9}, {%0,%1,%2,%3};"
        : "+f"(c[0]), "+f"(c[1]), "+f"(c[2]), "+f"(c[3])
        : "r"(a[0]), "r"(a[1]), "r"(a[2]), "r"(a[3]), "r"(b[0]), "r"(b[1]));
}

__device__ __forceinline__ float silu_f(float v) {
    return __fdividef(v, 1.0f + __expf(-v));
}

// ---------------- pass 0: conversions (2 x float4 per thread) ----------------
__global__ void cvt_x_kernel(const float* __restrict__ x) {
    size_t base = ((size_t)blockIdx.x * 256 + threadIdx.x) * 8;
    #pragma unroll
    for (int u = 0; u < 2; u++) {
        size_t i = base + u * 4;
        float4 v = *reinterpret_cast<const float4*>(x + i);
        int row = (int)(i >> 10);
        int col = (int)(i & 1023);
        int g = row & 7, b = row >> 3;
        __half2 h0 = __floats2half2_rn(v.x, v.y);
        __half2 h1 = __floats2half2_rn(v.z, v.w);
        __half2* d = reinterpret_cast<__half2*>(g_xh + (((size_t)(g * B_N + b)) << 10) + col);
        d[0] = h0; d[1] = h1;
    }
}

__global__ void cvt_w_all_kernel(const float* __restrict__ Wg,
                                 const float* __restrict__ Wu,
                                 const float* __restrict__ Wd) {
    int which = blockIdx.x >> 13;                 // 8192 blocks per weight
    const float* s = (which == 0) ? Wg : (which == 1) ? Wu : Wd;
    __half* dst    = (which == 0) ? g_wgh : (which == 1) ? g_wuh : g_wdh;
    size_t base = ((size_t)(blockIdx.x & 8191) * 256 + threadIdx.x) * 8;
    #pragma unroll
    for (int u = 0; u < 2; u++) {
        size_t i = base + u * 4;
        float4 v = *reinterpret_cast<const float4*>(s + i);
        __half2 h0 = __floats2half2_rn(v.x, v.y);
        __half2 h1 = __floats2half2_rn(v.z, v.w);
        __half2* d = reinterpret_cast<__half2*>(dst + i);
        d[0] = h0; d[1] = h1;
    }
}

// ---------------- pass 1: FUSED gate+up -> SwiGLU -> g_hid ----------------
// CTA tile 128(M)x64(N_H), BK=64, 128 threads (4 warps as 2Mx2N), warp tile 64x32.
// Dual accumulators. 3-stage cp.async; prefetch SPREAD as one quarter per
// ks body (issued after that ks's MMAs, in the MMA issue shadow).
#define GU_A_STAGE (128 * 64 * 2)               // 16KB
#define GU_B_STAGE (64 * 64 * 2)                // 8KB per B matrix
#define GU_STAGE   (GU_A_STAGE + 2 * GU_B_STAGE) // 32KB
#define GU_SMEM    (3 * GU_STAGE)               // 96KB

__global__ void __launch_bounds__(128, 2) gemm_gu_kernel() {
    extern __shared__ __align__(1024) __half smem[];

    int tid = threadIdx.x, l = tid & 31, wid = tid >> 5;
    int wm = wid & 1, wn = wid >> 1;            // 2x2 warp grid
    int g = blockIdx.z, m0 = blockIdx.y * 128, n0 = blockIdx.x * 64;

    const __half* A  = g_xh  + ((size_t)g * B_N + m0) * D_N;
    const __half* Bg = g_wgh + ((size_t)g * H_N + n0) * D_N;
    const __half* Bu = g_wuh + ((size_t)g * H_N + n0) * D_N;

    uint32_t sbase = smem_u32(smem);
    uint32_t sAu[3], sBgu[3], sBuu[3];
    #pragma unroll
    for (int s = 0; s < 3; s++) {
        sAu[s]  = sbase + s * GU_STAGE;
        sBgu[s] = sAu[s] + GU_A_STAGE;
        sBuu[s] = sBgu[s] + GU_B_STAGE;
    }

    float accG[4][4][4], accU[4][4][4];
    #pragma unroll
    for (int i = 0; i < 4; i++)
        #pragma unroll
        for (int j = 0; j < 4; j++)
            #pragma unroll
            for (int q = 0; q < 4; q++) { accG[i][j][q] = 0.0f; accU[i][j][q] = 0.0f; }

    // quarter q of the chunk load: 2 A rows-groups + 1 Bg + 1 Bu per thread
    auto load_quarter = [&](int kc, int s, int q) {
        int k0 = kc * 64;
        #pragma unroll
        for (int i = 0; i < 2; i++) {            // A: rows [q*32 .. q*32+32)
            int linear = tid + (q * 2 + i) * 128;
            int r = linear >> 3, c = linear & 7;
            cpa16(sAu[s] + swz64(r, c), A + (size_t)r * D_N + k0 + c * 8);
        }
        {                                        // Bg/Bu: rows [q*16 .. q*16+16)
            int linear = tid + q * 128;
            int r = linear >> 3, c = linear & 7;
            uint32_t so = swz64(r, c);
            size_t go = (size_t)r * D_N + k0 + c * 8;
            cpa16(sBgu[s] + so, Bg + go);
            cpa16(sBuu[s] + so, Bu + go);
        }
    };
    auto load_tiles = [&](int kc, int s) {
        #pragma unroll
        for (int q = 0; q < 4; q++) load_quarter(kc, s, q);
    };

    const int NKC = D_N / 64;                // 16
    load_tiles(0, 0); cpa_commit();
    load_tiles(1, 1); cpa_commit();
    cpa_wait1();
    __syncthreads();

    int s = 0, sl = 2;
    for (int kc = 0; kc < NKC; kc++) {
        bool more = (kc + 2 < NKC);
        #pragma unroll
        for (int ks = 0; ks < 4; ks++) {     // 4 k-steps of 16 per chunk
            uint32_t af[4][4], bg[4][2], bu[4][2];
            #pragma unroll
            for (int i = 0; i < 4; i++) {    // A: m16k16 fragments (64 rows)
                int r = wm * 64 + i * 16 + (l & 15);
                int c = ks * 2 + (l >> 4);
                ldsm_x4(af[i][0], af[i][1], af[i][2], af[i][3], sAu[s] + swz64(r, c));
            }
            #pragma unroll
            for (int p = 0; p < 2; p++) {    // B: two 8-row blocks per x4 (32 cols)
                int j = 2 * p;
                int r = wn * 32 + j * 8 + ((l & 16) >> 1) + (l & 7);
                int c = ks * 2 + ((l >> 3) & 1);
                uint32_t so = swz64(r, c);
                ldsm_x4(bg[j][0], bg[j][1], bg[j + 1][0], bg[j + 1][1], sBgu[s] + so);
                ldsm_x4(bu[j][0], bu[j][1], bu[j + 1][0], bu[j + 1][1], sBuu[s] + so);
            }
            #pragma unroll
            for (int i = 0; i < 4; i++)
                #pragma unroll
                for (int j = 0; j < 4; j++) {
                    mma16816(accG[i][j], af[i], bg[j]);
                    mma16816(accU[i][j], af[i], bu[j]);
                }
            if (more) load_quarter(kc + 2, sl, ks);   // in the MMA issue shadow
        }

        if (more) { cpa_commit(); cpa_wait1(); }
        else      { cpa_wait0(); }
        __syncthreads();

        s  = (s  == 2) ? 0 : s  + 1;
        sl = (sl == 2) ? 0 : sl + 1;
    }

    // epilogue: silu(gate)*up (fp32, unrounded) -> fp16 hidden
    int rq = l >> 2;          // 0..7
    int cq = 2 * (l & 3);     // 0,2,4,6
    #pragma unroll
    for (int i = 0; i < 4; i++) {
        int mrow0 = m0 + wm * 64 + i * 16 + rq;
        #pragma unroll
        for (int j = 0; j < 4; j++) {
            int col = n0 + wn * 32 + j * 8 + cq;
            float h0 = silu_f(accG[i][j][0]) * accU[i][j][0];
            float h1 = silu_f(accG[i][j][1]) * accU[i][j][1];
            float h2 = silu_f(accG[i][j][2]) * accU[i][j][2];
            float h3 = silu_f(accG[i][j][3]) * accU[i][j][3];
            __half2* p0 = reinterpret_cast<__half2*>(
                g_hid + ((size_t)g * B_N + mrow0) * H_N + col);
            __half2* p1 = reinterpret_cast<__half2*>(
                g_hid + ((size_t)g * B_N + mrow0 + 8) * H_N + col);
            *p0 = __floats2half2_rn(h0, h1);
            *p1 = __floats2half2_rn(h2, h3);
        }
    }
}

// ---------------- pass 2: down projection ----------------
// CTA tile 128x128, BK=64, 128 threads (4 warps as 2Mx2N), warp tile 64x64.
#define A_STAGE (128 * 64 * 2)              // 16KB
#define B_STAGE (128 * 64 * 2)              // 16KB
#define STAGE_BYTES (A_STAGE + B_STAGE)     // 32KB
#define SMEM_DYN (3 * STAGE_BYTES)          // 96KB

__global__ void __launch_bounds__(128, 2) gemm_d_kernel(float* __restrict__ out) {
    extern __shared__ __align__(1024) __half smem[];

    int tid = threadIdx.x, l = tid & 31, wid = tid >> 5;
    int wm = wid & 1, wn = wid >> 1;            // 2x2 warp grid
    int g = blockIdx.z, m0 = blockIdx.y * 128, n0 = blockIdx.x * 128;

    const __half* A = g_hid + ((size_t)g * B_N + m0) * H_N;
    const __half* B = g_wdh + ((size_t)g * O_N + n0) * H_N;

    uint32_t sbase = smem_u32(smem);
    uint32_t sAu[3] = { sbase,           sbase + STAGE_BYTES,           sbase + 2 * STAGE_BYTES };
    uint32_t sBu[3] = { sbase + A_STAGE, sbase + STAGE_BYTES + A_STAGE, sbase + 2 * STAGE_BYTES + A_STAGE };

    float acc[4][8][4];
    #pragma unroll
    for (int i = 0; i < 4; i++)
        #pragma unroll
        for (int j = 0; j < 8; j++)
            #pragma unroll
            for (int q = 0; q < 4; q++) acc[i][j][q] = 0.0f;

    // quarter q: 2 A row-groups + 2 B row-groups per thread
    auto load_quarter = [&](int kc, int s, int q) {
        int k0 = kc * 64;
        #pragma unroll
        for (int i = 0; i < 2; i++) {
            int linear = tid + (q * 2 + i) * 128;
            int r = linear >> 3, c = linear & 7;
            cpa16(sAu[s] + swz64(r, c), A + (size_t)r * H_N + k0 + c * 8);
        }
        #pragma unroll
        for (int i = 0; i < 2; i++) {
            int linear = tid + (q * 2 + i) * 128;
            int r = linear >> 3, c = linear & 7;
            cpa16(sBu[s] + swz64(r, c), B + (size_t)r * H_N + k0 + c * 8);
        }
    };
    auto load_tiles = [&](int kc, int s) {
        #pragma unroll
        for (int q = 0; q < 4; q++) load_quarter(kc, s, q);
    };

    const int NKC = H_N / 64;               // 32
    load_tiles(0, 0); cpa_commit();
    load_tiles(1, 1); cpa_commit();
    cpa_wait1();
    __syncthreads();

    int s = 0, sl = 2;
    for (int kc = 0; kc < NKC; kc++) {
        bool more = (kc + 2 < NKC);
        #pragma unroll
        for (int ks = 0; ks < 4; ks++) {
            uint32_t af[4][4], bf[8][2];
            #pragma unroll
            for (int i = 0; i < 4; i++) {
                int r = wm * 64 + i * 16 + (l & 15);
                int c = ks * 2 + (l >> 4);
                ldsm_x4(af[i][0], af[i][1], af[i][2], af[i][3], sAu[s] + swz64(r, c));
            }
            #pragma unroll
            for (int p = 0; p < 4; p++) {
                int j = 2 * p;
                int r = wn * 64 + j * 8 + ((l & 16) >> 1) + (l & 7);
                int c = ks * 2 + ((l >> 3) & 1);
                ldsm_x4(bf[j][0], bf[j][1], bf[j + 1][0], bf[j + 1][1],
                        sBu[s] + swz64(r, c));
            }
            #pragma unroll
            for (int i = 0; i < 4; i++)
                #pragma unroll
                for (int j = 0; j < 8; j++)
                    mma16816(acc[i][j], af[i], bf[j]);
            if (more) load_quarter(kc + 2, sl, ks);   // in the MMA issue shadow
        }

        if (more) { cpa_commit(); cpa_wait1(); }
        else      { cpa_wait0(); }
        __syncthreads();

        s  = (s  == 2) ? 0 : s  + 1;
        sl = (sl == 2) ? 0 : sl + 1;
    }

    int rq = l >> 2;
    int cq = 2 * (l & 3);
    #pragma unroll
    for (int i = 0; i < 4; i++) {
        int mrow0 = m0 + wm * 64 + i * 16 + rq;
        #pragma unroll
        for (int j = 0; j < 8; j++) {
            int col = n0 + wn * 64 + j * 8 + cq;
            float2* p0 = reinterpret_cast<float2*>(
                out + ((size_t)(mrow0 * G_N + g)) * O_N + col);
            float2* p1 = reinterpret_cast<float2*>(
                out + ((size_t)((mrow0 + 8) * G_N + g)) * O_N + col);
            *p0 = make_float2(acc[i][j][0], acc[i][j][1]);
            *p1 = make_float2(acc[i][j][2], acc[i][j][3]);
        }
    }
}

// ---------------- launcher ----------------
extern "C" void kernel_launch(void* const* d_in, const int* in_sizes, int n_in,
                              void* d_out, int out_size) {
    (void)in_sizes; (void)n_in; (void)out_size;
    const float* x  = (const float*)d_in[0];
    const float* Wg = (const float*)d_in[1];
    const float* Wu = (const float*)d_in[2];
    const float* Wd = (const float*)d_in[3];
    float* out = (float*)d_out;

    cudaFuncSetAttribute(gemm_gu_kernel, cudaFuncAttributeMaxDynamicSharedMemorySize, GU_SMEM);
    cudaFuncSetAttribute(gemm_d_kernel,  cudaFuncAttributeMaxDynamicSharedMemorySize, SMEM_DYN);

    cvt_x_kernel<<<32768, 256>>>(x);               // 8 floats per thread
    cvt_w_all_kernel<<<24576, 256>>>(Wg, Wu, Wd);  // 8192 blocks per weight

    gemm_gu_kernel<<<dim3(32, 64, 8), 128, GU_SMEM>>>();     // fused gate+up+SwiGLU
    gemm_d_kernel<<<dim3(8, 64, 8), 128, SMEM_DYN>>>(out);   // down proj
}